// round 4
// baseline (speedup 1.0000x reference)
#include <cuda_runtime.h>
#include <cstdint>

#define B_DIM 16
#define L_DIM 2048
#define F_DIM 512

#define CTA_M 128
#define CTA_N 128
#define KC    32
#define NCH   (L_DIM / KC)   /* 64 */
#define THREADS 256

/* A smem: 2 buffers x 128 rows x 32 words (XOR-swizzled, no pad) + 128 rowsums */
#define A_BUF_WORDS 4096
#define SMEM_FLOATS (2 * A_BUF_WORDS + 128)
#define SMEM_BYTES  (SMEM_FLOATS * 4)    /* 33280 */

__device__ __forceinline__ uint32_t f2tf32(float f) {
    uint32_t o;
    asm("cvt.rna.tf32.f32 %0, %1;" : "=r"(o) : "f"(f));
    return o;
}

__device__ __forceinline__ void mma_tf32(float* c, const uint32_t* a, const uint32_t* b) {
    asm volatile(
        "mma.sync.aligned.m16n8k8.row.col.f32.tf32.tf32.f32 "
        "{%0,%1,%2,%3}, {%4,%5,%6,%7}, {%8,%9}, {%0,%1,%2,%3};"
        : "+f"(c[0]), "+f"(c[1]), "+f"(c[2]), "+f"(c[3])
        : "r"(a[0]), "r"(a[1]), "r"(a[2]), "r"(a[3]), "r"(b[0]), "r"(b[1]));
}

__global__ void __launch_bounds__(THREADS, 2)
FrameAugment_39771397161402_kernel(const float* __restrict__ feature,
                                   const float* __restrict__ noise,
                                   float* __restrict__ out)
{
    extern __shared__ float sm[];
    float* Rs = sm + 2 * A_BUF_WORDS;

    const int tid  = threadIdx.x;
    const int w    = tid >> 5;
    const int lane = tid & 31;
    const int q    = lane >> 2;     /* 0..7 */
    const int qt   = lane & 3;      /* 0..3 */
    const int wm   = w >> 2;        /* 0..1  -> 64 rows */
    const int wn   = w & 3;         /* 0..3  -> 32 cols */

    const int b  = blockIdx.z;
    const int m0 = blockIdx.x * CTA_M;
    const int n0 = blockIdx.y * CTA_N;

    const float* nptr = noise   + ((size_t)b * L_DIM + m0) * L_DIM;
    const float* fptr = feature + (size_t)b * L_DIM * F_DIM + n0;
    float*       optr = out     + ((size_t)b * L_DIM + m0) * F_DIM + n0;

    float c[4][4][4];
    #pragma unroll
    for (int f = 0; f < 4; ++f)
        #pragma unroll
        for (int g = 0; g < 4; ++g)
            #pragma unroll
            for (int k = 0; k < 4; ++k) c[f][g][k] = 0.0f;

    float  rsum[2] = {0.f, 0.f};
    float4 stA[2];
    float  bbf[32];   /* raw B floats for one full chunk, fragment layout */

/* A half-tile (16 of 32 cols) LDG staging */
#define LOAD_A_H(H, IT)                                                         \
    {                                                                           \
        _Pragma("unroll")                                                       \
        for (int qq = 0; qq < 2; ++qq) {                                        \
            const int v = tid + 256 * qq;                                       \
            const int row = v >> 2, c4 = v & 3;                                 \
            stA[qq] = *(const float4*)(nptr + (size_t)row * L_DIM               \
                        + (IT) * KC + (H) * 16 + c4 * 4);                       \
        }                                                                       \
    }

/* exp + rowsum + swizzled STS.128 */
#define COMMIT_A_H(H, BUF)                                                      \
    {                                                                           \
        _Pragma("unroll")                                                       \
        for (int qq = 0; qq < 2; ++qq) {                                        \
            const int v = tid + 256 * qq;                                       \
            const int row = v >> 2, c4 = v & 3;                                 \
            const float e0 = __expf(stA[qq].x), e1 = __expf(stA[qq].y);         \
            const float e2 = __expf(stA[qq].z), e3 = __expf(stA[qq].w);         \
            float s = (e0 + e1) + (e2 + e3);                                    \
            s += __shfl_xor_sync(0xFFFFFFFFu, s, 1);                            \
            s += __shfl_xor_sync(0xFFFFFFFFu, s, 2);                            \
            rsum[qq] += s;                                                      \
            const int fx  = ((row & 1) << 2) | ((row >> 1) & 3);                \
            const int wrd = (BUF) * A_BUF_WORDS + row * 32                      \
                          + (((c4 + 4 * (H)) ^ fx) << 2);                       \
            uint4 u;                                                            \
            u.x = f2tf32(e0); u.y = f2tf32(e1); u.z = f2tf32(e2); u.w = f2tf32(e3); \
            *(uint4*)((uint32_t*)sm + wrd) = u;                                 \
        }                                                                       \
    }

/* B fragments straight from GMEM (L2), raw fp32 bits; cvt at use site */
#define LOAD_B(IT)                                                              \
    {                                                                           \
        _Pragma("unroll")                                                       \
        for (int ks = 0; ks < 4; ++ks) {                                        \
            _Pragma("unroll")                                                   \
            for (int g = 0; g < 4; ++g) {                                       \
                const float* p = fptr + (size_t)((IT) * KC + ks * 8 + qt) * F_DIM \
                               + wn * 32 + g * 8 + q;                           \
                bbf[(ks * 4 + g) * 2 + 0] = p[0];                               \
                bbf[(ks * 4 + g) * 2 + 1] = p[4 * F_DIM];                       \
            }                                                                   \
        }                                                                       \
    }

/* one K=8 step: swizzled A LDS + B cvt + 16 MMAs */
#define MMA_KS(KS, BUF)                                                         \
    {                                                                           \
        const uint32_t* Ab = (const uint32_t*)sm + (BUF) * A_BUF_WORDS;         \
        uint32_t a[4][4];                                                       \
        _Pragma("unroll")                                                       \
        for (int f = 0; f < 4; ++f) {                                           \
            const int ar = wm * 64 + f * 16 + q;                                \
            const int fx = ((ar & 1) << 2) | ((ar >> 1) & 3);                   \
            const int w0 = ar * 32 + (((2 * (KS)) ^ fx) << 2) + qt;             \
            const int w1 = ar * 32 + (((2 * (KS) + 1) ^ fx) << 2) + qt;         \
            a[f][0] = Ab[w0];                                                   \
            a[f][1] = Ab[w0 + 256];                                             \
            a[f][2] = Ab[w1];                                                   \
            a[f][3] = Ab[w1 + 256];                                             \
        }                                                                       \
        uint32_t br[4][2];                                                      \
        _Pragma("unroll")                                                       \
        for (int g = 0; g < 4; ++g) {                                           \
            br[g][0] = f2tf32(bbf[((KS) * 4 + g) * 2 + 0]);                     \
            br[g][1] = f2tf32(bbf[((KS) * 4 + g) * 2 + 1]);                     \
        }                                                                       \
        _Pragma("unroll")                                                       \
        for (int f = 0; f < 4; ++f)                                             \
            _Pragma("unroll")                                                   \
            for (int g = 0; g < 4; ++g)                                         \
                mma_tf32(c[f][g], a[f], br[g]);                                 \
    }

    /* ---------------- prologue: fill A buf0 + B chunk0 ---------------- */
    LOAD_A_H(0, 0);
    COMMIT_A_H(0, 0);
    LOAD_A_H(1, 0);
    COMMIT_A_H(1, 0);
    LOAD_B(0);
    __syncthreads();

    /* ---------------- main loop ---------------- */
    #pragma unroll 2
    for (int it = 0; it < NCH; ++it) {
        const int cur = it & 1;
        const int nxt = cur ^ 1;
        const bool more = (it + 1 < NCH);

        if (more) LOAD_A_H(0, it + 1);
        MMA_KS(0, cur);
        MMA_KS(1, cur);
        if (more) { COMMIT_A_H(0, nxt); LOAD_A_H(1, it + 1); }
        MMA_KS(2, cur);
        MMA_KS(3, cur);
        if (more) { LOAD_B(it + 1); COMMIT_A_H(1, nxt); }
        __syncthreads();
    }

    /* ---------------- row sums -> smem ---------------- */
    if ((tid & 3) == 0) {
        #pragma unroll
        for (int qq = 0; qq < 2; ++qq)
            Rs[(tid + 256 * qq) >> 2] = rsum[qq];
    }
    __syncthreads();

    /* ---------------- epilogue: divide + store ---------------- */
    #pragma unroll
    for (int f = 0; f < 4; ++f) {
        const int r0 = wm * 64 + f * 16 + q;
        const int r1 = r0 + 8;
        const float inv0 = 1.0f / Rs[r0];
        const float inv1 = 1.0f / Rs[r1];
        #pragma unroll
        for (int g = 0; g < 4; ++g) {
            const int col = wn * 32 + g * 8 + 2 * qt;
            float2 lo, hi;
            lo.x = c[f][g][0] * inv0;
            lo.y = c[f][g][1] * inv0;
            hi.x = c[f][g][2] * inv1;
            hi.y = c[f][g][3] * inv1;
            *(float2*)(optr + (size_t)r0 * F_DIM + col) = lo;
            *(float2*)(optr + (size_t)r1 * F_DIM + col) = hi;
        }
    }
}

extern "C" void kernel_launch(void* const* d_in, const int* in_sizes, int n_in,
                              void* d_out, int out_size) {
    (void)in_sizes; (void)n_in; (void)out_size;
    const float* feature = (const float*)d_in[0];
    const float* noise   = (const float*)d_in[1];
    float* out = (float*)d_out;

    cudaFuncSetAttribute(FrameAugment_39771397161402_kernel,
                         cudaFuncAttributeMaxDynamicSharedMemorySize, SMEM_BYTES);

    dim3 grid(L_DIM / CTA_M, F_DIM / CTA_N, B_DIM);   /* 16 x 4 x 16 = 1024 CTAs */
    FrameAugment_39771397161402_kernel<<<grid, THREADS, SMEM_BYTES>>>(feature, noise, out);
}

// round 5
// speedup vs baseline: 2.8992x; 2.8992x over previous
#include <cuda_runtime.h>
#include <cuda_fp16.h>
#include <cstdint>

#define B_DIM 16
#define L_DIM 2048
#define F_DIM 512

#define CTA_M 128
#define CTA_N 256
#define KC    32
#define NCH   (L_DIM / KC)   /* 64 */
#define NSTAGE 4
#define THREADS 256

#define WSCALE 1024.0f       /* weights stored x1024 to avoid fp16 subnormals */
#define INV_WSCALE (1.0f / 1024.0f)

/* scratch: normalized softmax weights (fp16, x1024) and fp16 feature */
__device__ __half g_expw[(size_t)B_DIM * L_DIM * L_DIM];   /* 128 MB */
__device__ __half g_featx[(size_t)B_DIM * L_DIM * F_DIM];  /*  32 MB */

/* GEMM smem: per stage A 128x32 half (8KB) + B 32x256 half (16KB) */
#define A_STAGE 8192
#define B_STAGE 16384
#define STAGE_BYTES (A_STAGE + B_STAGE)
#define SMEM_BYTES (NSTAGE * STAGE_BYTES)   /* 98304 */

/* ============== prepass 1: softmax rows -> fp16 weights (x1024) ============ */
__global__ void __launch_bounds__(256, 8)
prep_softmax(const float* __restrict__ noise)
{
    __shared__ float red[8];
    const int tid  = threadIdx.x;
    const int lane = tid & 31;
    const int w    = tid >> 5;
    const size_t r = blockIdx.x;

    const float4* src = (const float4*)(noise + r * L_DIM);
    const float4 v0 = src[tid];
    const float4 v1 = src[tid + 256];

    float e0 = __expf(v0.x), e1 = __expf(v0.y), e2 = __expf(v0.z), e3 = __expf(v0.w);
    float e4 = __expf(v1.x), e5 = __expf(v1.y), e6 = __expf(v1.z), e7 = __expf(v1.w);

    float s = ((e0 + e1) + (e2 + e3)) + ((e4 + e5) + (e6 + e7));
    #pragma unroll
    for (int o = 16; o; o >>= 1) s += __shfl_xor_sync(0xFFFFFFFFu, s, o);
    if (lane == 0) red[w] = s;
    __syncthreads();
    if (tid == 0) {
        float t = 0.f;
        #pragma unroll
        for (int i = 0; i < 8; ++i) t += red[i];
        red[0] = WSCALE / t;
    }
    __syncthreads();
    const float inv = red[0];

    uint2* dst = (uint2*)(g_expw + r * L_DIM);
    __half2 p0 = __floats2half2_rn(e0 * inv, e1 * inv);
    __half2 p1 = __floats2half2_rn(e2 * inv, e3 * inv);
    __half2 p2 = __floats2half2_rn(e4 * inv, e5 * inv);
    __half2 p3 = __floats2half2_rn(e6 * inv, e7 * inv);
    uint2 u0, u1;
    u0.x = *(uint32_t*)&p0; u0.y = *(uint32_t*)&p1;
    u1.x = *(uint32_t*)&p2; u1.y = *(uint32_t*)&p3;
    dst[tid]       = u0;
    dst[tid + 256] = u1;
}

/* ============== prepass 2: feature fp32 -> fp16 ============ */
__global__ void __launch_bounds__(256, 8)
prep_feat(const float* __restrict__ feat)
{
    const size_t i = (size_t)blockIdx.x * 256 + threadIdx.x;
    const float4 v = ((const float4*)feat)[i];
    __half2 p0 = __floats2half2_rn(v.x, v.y);
    __half2 p1 = __floats2half2_rn(v.z, v.w);
    uint2 u;
    u.x = *(uint32_t*)&p0; u.y = *(uint32_t*)&p1;
    ((uint2*)g_featx)[i] = u;
}

/* ============== main fp16 GEMM ============ */
__device__ __forceinline__ void mma_f16(float* c, const uint32_t* a, const uint32_t* b) {
    asm volatile(
        "mma.sync.aligned.m16n8k16.row.col.f32.f16.f16.f32 "
        "{%0,%1,%2,%3}, {%4,%5,%6,%7}, {%8,%9}, {%0,%1,%2,%3};"
        : "+f"(c[0]), "+f"(c[1]), "+f"(c[2]), "+f"(c[3])
        : "r"(a[0]), "r"(a[1]), "r"(a[2]), "r"(a[3]), "r"(b[0]), "r"(b[1]));
}

#define LDSM4(R, ADDR)                                                        \
    asm volatile("ldmatrix.sync.aligned.m8n8.x4.shared.b16 {%0,%1,%2,%3},[%4];" \
                 : "=r"((R)[0]), "=r"((R)[1]), "=r"((R)[2]), "=r"((R)[3]) : "r"(ADDR))

#define LDSM4T(R0, R1, R2, R3, ADDR)                                          \
    asm volatile("ldmatrix.sync.aligned.m8n8.x4.trans.shared.b16 {%0,%1,%2,%3},[%4];" \
                 : "=r"(R0), "=r"(R1), "=r"(R2), "=r"(R3) : "r"(ADDR))

#define CPA16(SADDR, GPTR)                                                    \
    asm volatile("cp.async.cg.shared.global [%0], [%1], 16;"                  \
                 :: "r"(SADDR), "l"(GPTR))

__global__ void __launch_bounds__(THREADS, 1)
FrameAugment_39771397161402_kernel(float* __restrict__ out)
{
    extern __shared__ char smraw[];
    uint32_t sbase;
    asm("{ .reg .u64 t; cvta.to.shared.u64 t, %1; cvt.u32.u64 %0, t; }"
        : "=r"(sbase) : "l"(smraw));

    const int tid  = threadIdx.x;
    const int lane = tid & 31;
    const int w    = tid >> 5;
    const int q    = lane >> 2;
    const int qt   = lane & 3;
    const int wm   = w >> 2;      /* 0..1 : 64 rows  */
    const int wn   = w & 3;       /* 0..3 : 64 cols  */

    const int b  = blockIdx.z;
    const int m0 = blockIdx.x * CTA_M;
    const int n0 = blockIdx.y * CTA_N;

    const __half* aG = g_expw + ((size_t)b * L_DIM + m0) * L_DIM;
    const __half* bG = g_featx + (size_t)b * L_DIM * F_DIM + n0;
    float*        oG = out + ((size_t)b * L_DIM + m0) * F_DIM + n0;

    /* ---- per-thread cp.async offsets ---- */
    const int arow = tid >> 2, ac = tid & 3;
    const uint32_t aoff = (uint32_t)arow * 64u + (uint32_t)((ac ^ ((arow >> 1) & 3)) << 4);
    const size_t   gaoff = (size_t)arow * L_DIM + ac * 8;
    const int bnc = tid & 31;
    const uint32_t boff = (uint32_t)w * 512u +
                          (uint32_t)(((bnc & 24) | ((bnc & 7) ^ w)) << 4);
    const size_t   gboff = (size_t)w * F_DIM + bnc * 8;

    /* ---- per-lane ldmatrix invariants ---- */
    const int l4   = lane >> 4;                            /* 0/1 */
    const int lk   = lane & 7;
    const int arw0 = wm * 64 + ((lane >> 3) & 1) * 8 + lk; /* A row base */
    const int akey = (arw0 >> 1) & 3;
    const int bk0  = ((lane >> 3) & 1) * 8 + lk;           /* B k base within k16 */

#define LOAD_STAGE(IT, SLOT)                                                   \
    {                                                                          \
        const uint32_t sa = sbase + (SLOT) * STAGE_BYTES + aoff;               \
        const __half* ga = aG + (size_t)(IT) * KC + gaoff;                     \
        CPA16(sa, ga);                                                         \
        CPA16(sa + 4096u, ga + (size_t)64 * L_DIM);                            \
        const uint32_t sb = sbase + (SLOT) * STAGE_BYTES + A_STAGE + boff;     \
        const __half* gb = bG + (size_t)(IT) * KC * F_DIM + gboff;             \
        CPA16(sb,          gb);                                                \
        CPA16(sb + 4096u,  gb + 8 * F_DIM);                                    \
        CPA16(sb + 8192u,  gb + 16 * F_DIM);                                   \
        CPA16(sb + 12288u, gb + 24 * F_DIM);                                   \
        asm volatile("cp.async.commit_group;");                                \
    }

    float c[4][8][4];
    #pragma unroll
    for (int f = 0; f < 4; ++f)
        #pragma unroll
        for (int g = 0; g < 8; ++g)
            #pragma unroll
            for (int k = 0; k < 4; ++k) c[f][g][k] = 0.f;

    /* ---- prologue: 3 stages in flight ---- */
    LOAD_STAGE(0, 0);
    LOAD_STAGE(1, 1);
    LOAD_STAGE(2, 2);

    /* ---- main loop ---- */
    #pragma unroll 4
    for (int it = 0; it < NCH; ++it) {
        const int slot = it & (NSTAGE - 1);

        asm volatile("cp.async.wait_group %0;" :: "n"(NSTAGE - 2));
        __syncthreads();

        if (it + NSTAGE - 1 < NCH) {
            LOAD_STAGE(it + NSTAGE - 1, (it + NSTAGE - 1) & (NSTAGE - 1));
        } else {
            asm volatile("cp.async.commit_group;");
        }

        const uint32_t Ab = sbase + slot * STAGE_BYTES;
        const uint32_t Bb = Ab + A_STAGE;

        #pragma unroll
        for (int s = 0; s < 2; ++s) {
            uint32_t a[4][4];
            #pragma unroll
            for (int f = 0; f < 4; ++f) {
                const uint32_t addr = Ab + (uint32_t)(arw0 + 16 * f) * 64u
                                    + (uint32_t)(((s * 2 + l4) ^ akey) << 4);
                LDSM4(a[f], addr);
            }
            uint32_t bb[8][2];
            #pragma unroll
            for (int j = 0; j < 4; ++j) {
                const uint32_t addr = Bb + (uint32_t)(s * 16 + bk0) * 512u
                                    + (uint32_t)((wn * 8 + ((j * 2 + l4) ^ lk)) << 4);
                uint32_t t0, t1, t2, t3;
                LDSM4T(t0, t1, t2, t3, addr);
                bb[2 * j][0] = t0; bb[2 * j][1] = t1;
                bb[2 * j + 1][0] = t2; bb[2 * j + 1][1] = t3;
            }
            #pragma unroll
            for (int f = 0; f < 4; ++f)
                #pragma unroll
                for (int g = 0; g < 8; ++g)
                    mma_f16(c[f][g], a[f], bb[g]);
        }
    }

    /* ---- epilogue: undo x1024 scale, store ---- */
    #pragma unroll
    for (int f = 0; f < 4; ++f) {
        const int r0 = wm * 64 + f * 16 + q;
        const int r1 = r0 + 8;
        #pragma unroll
        for (int g = 0; g < 8; ++g) {
            const int col = wn * 64 + g * 8 + 2 * qt;
            float2 lo, hi;
            lo.x = c[f][g][0] * INV_WSCALE;
            lo.y = c[f][g][1] * INV_WSCALE;
            hi.x = c[f][g][2] * INV_WSCALE;
            hi.y = c[f][g][3] * INV_WSCALE;
            *(float2*)(oG + (size_t)r0 * F_DIM + col) = lo;
            *(float2*)(oG + (size_t)r1 * F_DIM + col) = hi;
        }
    }
}

extern "C" void kernel_launch(void* const* d_in, const int* in_sizes, int n_in,
                              void* d_out, int out_size) {
    (void)in_sizes; (void)n_in; (void)out_size;
    const float* feature = (const float*)d_in[0];
    const float* noise   = (const float*)d_in[1];
    float* out = (float*)d_out;

    prep_softmax<<<B_DIM * L_DIM, 256>>>(noise);
    prep_feat<<<(B_DIM * L_DIM * F_DIM) / (256 * 4), 256>>>(feature);

    cudaFuncSetAttribute(FrameAugment_39771397161402_kernel,
                         cudaFuncAttributeMaxDynamicSharedMemorySize, SMEM_BYTES);
    dim3 grid(L_DIM / CTA_M, F_DIM / CTA_N, B_DIM);   /* 16 x 2 x 16 = 512 CTAs */
    FrameAugment_39771397161402_kernel<<<grid, THREADS, SMEM_BYTES>>>(out);
}

// round 6
// speedup vs baseline: 3.3591x; 1.1586x over previous
#include <cuda_runtime.h>
#include <cuda_fp16.h>
#include <cstdint>

#define B_DIM 16
#define L_DIM 2048
#define F_DIM 512

#define CTA_M 128
#define CTA_N 128
#define KC    32
#define NCH   (L_DIM / KC)   /* 64 */
#define NSTAGE 4
#define THREADS 256

#define WSCALE 1024.0f
#define INV_WSCALE (1.0f / 1024.0f)

__device__ __half g_expw[(size_t)B_DIM * L_DIM * L_DIM];   /* 128 MB */
__device__ __half g_featx[(size_t)B_DIM * L_DIM * F_DIM];  /*  32 MB */

/* GEMM smem: per stage A 128x32 half (8KB) + B 32x128 half (8KB) */
#define A_STAGE 8192
#define B_STAGE 8192
#define STAGE_BYTES (A_STAGE + B_STAGE)
#define SMEM_BYTES (NSTAGE * STAGE_BYTES)   /* 65536 per CTA, 2 CTAs/SM */

/* ============== prepass 1: softmax rows -> fp16 weights (x1024) ============ */
__global__ void __launch_bounds__(256, 8)
prep_softmax(const float* __restrict__ noise)
{
    __shared__ float red[8];
    const int tid  = threadIdx.x;
    const int lane = tid & 31;
    const int w    = tid >> 5;
    const size_t r = blockIdx.x;

    const float4* src = (const float4*)(noise + r * L_DIM);
    const float4 v0 = src[tid];
    const float4 v1 = src[tid + 256];

    float e0 = __expf(v0.x), e1 = __expf(v0.y), e2 = __expf(v0.z), e3 = __expf(v0.w);
    float e4 = __expf(v1.x), e5 = __expf(v1.y), e6 = __expf(v1.z), e7 = __expf(v1.w);

    float s = ((e0 + e1) + (e2 + e3)) + ((e4 + e5) + (e6 + e7));
    #pragma unroll
    for (int o = 16; o; o >>= 1) s += __shfl_xor_sync(0xFFFFFFFFu, s, o);
    if (lane == 0) red[w] = s;
    __syncthreads();
    if (tid == 0) {
        float t = 0.f;
        #pragma unroll
        for (int i = 0; i < 8; ++i) t += red[i];
        red[0] = WSCALE / t;
    }
    __syncthreads();
    const float inv = red[0];

    uint2* dst = (uint2*)(g_expw + r * L_DIM);
    __half2 p0 = __floats2half2_rn(e0 * inv, e1 * inv);
    __half2 p1 = __floats2half2_rn(e2 * inv, e3 * inv);
    __half2 p2 = __floats2half2_rn(e4 * inv, e5 * inv);
    __half2 p3 = __floats2half2_rn(e6 * inv, e7 * inv);
    uint2 u0, u1;
    u0.x = *(uint32_t*)&p0; u0.y = *(uint32_t*)&p1;
    u1.x = *(uint32_t*)&p2; u1.y = *(uint32_t*)&p3;
    dst[tid]       = u0;
    dst[tid + 256] = u1;
}

/* ============== prepass 2: feature fp32 -> fp16 ============ */
__global__ void __launch_bounds__(256, 8)
prep_feat(const float* __restrict__ feat)
{
    const size_t i = (size_t)blockIdx.x * 256 + threadIdx.x;
    const float4 v = ((const float4*)feat)[i];
    __half2 p0 = __floats2half2_rn(v.x, v.y);
    __half2 p1 = __floats2half2_rn(v.z, v.w);
    uint2 u;
    u.x = *(uint32_t*)&p0; u.y = *(uint32_t*)&p1;
    ((uint2*)g_featx)[i] = u;
}

/* ============== main fp16 GEMM ============ */
__device__ __forceinline__ void mma_f16(float* c, const uint32_t* a, const uint32_t* b) {
    asm volatile(
        "mma.sync.aligned.m16n8k16.row.col.f32.f16.f16.f32 "
        "{%0,%1,%2,%3}, {%4,%5,%6,%7}, {%8,%9}, {%0,%1,%2,%3};"
        : "+f"(c[0]), "+f"(c[1]), "+f"(c[2]), "+f"(c[3])
        : "r"(a[0]), "r"(a[1]), "r"(a[2]), "r"(a[3]), "r"(b[0]), "r"(b[1]));
}

#define LDSM4(R, ADDR)                                                        \
    asm volatile("ldmatrix.sync.aligned.m8n8.x4.shared.b16 {%0,%1,%2,%3},[%4];" \
                 : "=r"((R)[0]), "=r"((R)[1]), "=r"((R)[2]), "=r"((R)[3]) : "r"(ADDR))

#define LDSM4T(R0, R1, R2, R3, ADDR)                                          \
    asm volatile("ldmatrix.sync.aligned.m8n8.x4.trans.shared.b16 {%0,%1,%2,%3},[%4];" \
                 : "=r"(R0), "=r"(R1), "=r"(R2), "=r"(R3) : "r"(ADDR))

#define CPA16(SADDR, GPTR)                                                    \
    asm volatile("cp.async.cg.shared.global [%0], [%1], 16;"                  \
                 :: "r"(SADDR), "l"(GPTR))

__global__ void __launch_bounds__(THREADS, 2)
FrameAugment_39771397161402_kernel(float* __restrict__ out)
{
    extern __shared__ char smraw[];
    uint32_t sbase;
    asm("{ .reg .u64 t; cvta.to.shared.u64 t, %1; cvt.u32.u64 %0, t; }"
        : "=r"(sbase) : "l"(smraw));

    const int tid  = threadIdx.x;
    const int lane = tid & 31;
    const int w    = tid >> 5;
    const int q    = lane >> 2;
    const int qt   = lane & 3;
    const int wm   = w >> 2;      /* 0..1 : 64 rows */
    const int wn   = w & 3;       /* 0..3 : 32 cols */

    const int b  = blockIdx.z;
    const int m0 = blockIdx.x * CTA_M;
    const int n0 = blockIdx.y * CTA_N;

    const __half* aG = g_expw + ((size_t)b * L_DIM + m0) * L_DIM;
    const __half* bG = g_featx + (size_t)b * L_DIM * F_DIM + n0;
    float*        oG = out + ((size_t)b * L_DIM + m0) * F_DIM + n0;

    /* ---- A producer: 128 rows x 64B, rows tid>>2 and +64 ---- */
    const int arow = tid >> 2, ac = tid & 3;
    const uint32_t aoff = (uint32_t)arow * 64u + (uint32_t)((ac ^ ((arow >> 1) & 3)) << 4);
    const size_t   gaoff = (size_t)arow * L_DIM + ac * 8;

    /* ---- B producer: 32 rows x 256B, rows tid>>4 and +16, chunk tid&15 ---- */
    const int brow = tid >> 4, bc = tid & 15;
    const uint32_t boff = (uint32_t)brow * 256u +
                          (uint32_t)(((bc & 8) | ((bc & 7) ^ (brow & 7))) << 4);
    const size_t   gboff = (size_t)brow * F_DIM + bc * 8;

    /* ---- ldmatrix invariants ---- */
    const int l4   = lane >> 4;                            /* 0/1 */
    const int lk   = lane & 7;
    const int arw0 = wm * 64 + ((lane >> 3) & 1) * 8 + lk;
    const int akey = (arw0 >> 1) & 3;
    const int bk0  = ((lane >> 3) & 1) * 8 + lk;

#define LOAD_STAGE(IT, SLOT)                                                   \
    {                                                                          \
        const uint32_t sa = sbase + (SLOT) * STAGE_BYTES + aoff;               \
        const __half* ga = aG + (size_t)(IT) * KC + gaoff;                     \
        CPA16(sa, ga);                                                         \
        CPA16(sa + 4096u, ga + (size_t)64 * L_DIM);                            \
        const uint32_t sb = sbase + (SLOT) * STAGE_BYTES + A_STAGE + boff;     \
        const __half* gb = bG + (size_t)(IT) * KC * F_DIM + gboff;             \
        CPA16(sb,          gb);                                                \
        CPA16(sb + 4096u,  gb + 16 * F_DIM);                                   \
        asm volatile("cp.async.commit_group;");                                \
    }

    float c[4][4][4];
    #pragma unroll
    for (int f = 0; f < 4; ++f)
        #pragma unroll
        for (int g = 0; g < 4; ++g)
            #pragma unroll
            for (int k = 0; k < 4; ++k) c[f][g][k] = 0.f;

    LOAD_STAGE(0, 0);
    LOAD_STAGE(1, 1);
    LOAD_STAGE(2, 2);

    #pragma unroll 4
    for (int it = 0; it < NCH; ++it) {
        const int slot = it & (NSTAGE - 1);

        asm volatile("cp.async.wait_group %0;" :: "n"(NSTAGE - 2));
        __syncthreads();

        if (it + NSTAGE - 1 < NCH) {
            LOAD_STAGE(it + NSTAGE - 1, (it + NSTAGE - 1) & (NSTAGE - 1));
        } else {
            asm volatile("cp.async.commit_group;");
        }

        const uint32_t Ab = sbase + slot * STAGE_BYTES;
        const uint32_t Bb = Ab + A_STAGE;

        #pragma unroll
        for (int s = 0; s < 2; ++s) {
            uint32_t a[4][4];
            #pragma unroll
            for (int f = 0; f < 4; ++f) {
                const uint32_t addr = Ab + (uint32_t)(arw0 + 16 * f) * 64u
                                    + (uint32_t)(((s * 2 + l4) ^ akey) << 4);
                LDSM4(a[f], addr);
            }
            uint32_t bb[4][2];
            #pragma unroll
            for (int j = 0; j < 2; ++j) {
                const int cidx = wn * 4 + j * 2 + l4;
                const uint32_t addr = Bb + (uint32_t)(s * 16 + bk0) * 256u
                                    + (uint32_t)((((cidx & 8) | ((cidx & 7) ^ lk))) << 4);
                uint32_t t0, t1, t2, t3;
                LDSM4T(t0, t1, t2, t3, addr);
                bb[2 * j][0] = t0; bb[2 * j][1] = t1;
                bb[2 * j + 1][0] = t2; bb[2 * j + 1][1] = t3;
            }
            #pragma unroll
            for (int f = 0; f < 4; ++f)
                #pragma unroll
                for (int g = 0; g < 4; ++g)
                    mma_f16(c[f][g], a[f], bb[g]);
        }
    }

    /* ---- epilogue: undo x1024 scale, store ---- */
    #pragma unroll
    for (int f = 0; f < 4; ++f) {
        const int r0 = wm * 64 + f * 16 + q;
        const int r1 = r0 + 8;
        #pragma unroll
        for (int g = 0; g < 4; ++g) {
            const int col = wn * 32 + g * 8 + 2 * qt;
            float2 lo, hi;
            lo.x = c[f][g][0] * INV_WSCALE;
            lo.y = c[f][g][1] * INV_WSCALE;
            hi.x = c[f][g][2] * INV_WSCALE;
            hi.y = c[f][g][3] * INV_WSCALE;
            *(float2*)(oG + (size_t)r0 * F_DIM + col) = lo;
            *(float2*)(oG + (size_t)r1 * F_DIM + col) = hi;
        }
    }
}

extern "C" void kernel_launch(void* const* d_in, const int* in_sizes, int n_in,
                              void* d_out, int out_size) {
    (void)in_sizes; (void)n_in; (void)out_size;
    const float* feature = (const float*)d_in[0];
    const float* noise   = (const float*)d_in[1];
    float* out = (float*)d_out;

    prep_softmax<<<B_DIM * L_DIM, 256>>>(noise);
    prep_feat<<<(B_DIM * L_DIM * F_DIM) / (256 * 4), 256>>>(feature);

    cudaFuncSetAttribute(FrameAugment_39771397161402_kernel,
                         cudaFuncAttributeMaxDynamicSharedMemorySize, SMEM_BYTES);
    dim3 grid(L_DIM / CTA_M, F_DIM / CTA_N, B_DIM);   /* 16 x 4 x 16 = 1024 CTAs */
    FrameAugment_39771397161402_kernel<<<grid, THREADS, SMEM_BYTES>>>(out);
}